// round 10
// baseline (speedup 1.0000x reference)
#include <cuda_runtime.h>
#include <cuda_fp16.h>
#include <cuda_bf16.h>

// Problem constants (from reference_code)
#define N_PATHS  10000000
#define MAX_LEN  3
#define N_NODES  100000
#define HIDDEN   128

// fp16 planar projection table: g_t16[l * N_NODES + node], 600 KB total.
__device__ __half        g_t16[3 * N_NODES];
// Monotonic device-wide barrier counter (never reset; target computed per pass)
__device__ unsigned int  g_bar;

// ---------------------------------------------------------------------------
// Fused persistent kernel.
// Phase 1: proj[l][node] = dot(feature[node], W[l][0]) -> fp16 table.
//          Warp-per-4-nodes, grid-strided over all nodes.
// Barrier: device-wide monotonic atomic barrier (all blocks resident by
//          construction: grid sized from the occupancy API).
// Phase 2: gather + masked mean, exact R7 inner loop (at the L1tex wavefront
//          floor; do not perturb), grid-strided over path quads.
// ---------------------------------------------------------------------------
__global__ void __launch_bounds__(256, 8)
fused_kernel(const float* __restrict__ nf, const float* __restrict__ W,
             const int* __restrict__ paths, float* __restrict__ out) {
    const int tid  = threadIdx.x;
    const int lane = tid & 31;

    // ---------------- Phase 1: projection table ----------------
    {
        const float4 w0 = __ldg(((const float4*)W) + 0  + lane);
        const float4 w1 = __ldg(((const float4*)W) + 32 + lane);
        const float4 w2 = __ldg(((const float4*)W) + 64 + lane);

        const int gwarp      = (blockIdx.x * blockDim.x + tid) >> 5;
        const int totalWarps = (gridDim.x * blockDim.x) >> 5;

        for (int n0 = gwarp * 4; n0 < N_NODES; n0 += totalWarps * 4) {
            float4 f[4];
            #pragma unroll
            for (int i = 0; i < 4; i++)
                f[i] = __ldcs(((const float4*)nf) + (size_t)(n0 + i) * 32 + lane);

            #pragma unroll
            for (int i = 0; i < 4; i++) {
                float s0 = f[i].x*w0.x + f[i].y*w0.y + f[i].z*w0.z + f[i].w*w0.w;
                float s1 = f[i].x*w1.x + f[i].y*w1.y + f[i].z*w1.z + f[i].w*w1.w;
                float s2 = f[i].x*w2.x + f[i].y*w2.y + f[i].z*w2.z + f[i].w*w2.w;

                #pragma unroll
                for (int o = 16; o > 0; o >>= 1) {
                    s0 += __shfl_xor_sync(0xFFFFFFFFu, s0, o);
                    s1 += __shfl_xor_sync(0xFFFFFFFFu, s1, o);
                    s2 += __shfl_xor_sync(0xFFFFFFFFu, s2, o);
                }

                if (lane == 0) {
                    const int node = n0 + i;
                    g_t16[0 * N_NODES + node] = __float2half(s0);
                    g_t16[1 * N_NODES + node] = __float2half(s1);
                    g_t16[2 * N_NODES + node] = __float2half(s2);
                }
            }
        }
    }

    // ---------------- Device-wide barrier (monotonic counter) ----------------
    __syncthreads();
    if (tid == 0) {
        __threadfence();  // table stores visible at GPU scope before arrive
        const unsigned int old    = atomicAdd(&g_bar, 1u) + 1u;
        const unsigned int target =
            ((old - 1u) / gridDim.x + 1u) * gridDim.x;
        for (;;) {
            unsigned int v;
            asm volatile("ld.global.acquire.gpu.u32 %0, [%1];"
                         : "=r"(v) : "l"(&g_bar));
            if (v >= target) break;
            __nanosleep(64);
        }
    }
    __syncthreads();

    // ---------------- Phase 2: gather + masked mean (R7 loop) ----------------
    const long long QT     = N_PATHS / 4;  // 2.5M quads
    const long long stride = (long long)gridDim.x * blockDim.x;

    for (long long q = (long long)blockIdx.x * blockDim.x + tid;
         q < QT; q += stride) {
        const int4* p4 = ((const int4*)paths) + q * 3;
        int4 v0 = __ldcs(p4 + 0);
        int4 v1 = __ldcs(p4 + 1);
        int4 v2 = __ldcs(p4 + 2);

        int idx[12] = { v0.x, v0.y, v0.z, v0.w,
                        v1.x, v1.y, v1.z, v1.w,
                        v2.x, v2.y, v2.z, v2.w };

        float4 res;
        float* r = (float*)&res;

        #pragma unroll
        for (int k = 0; k < 4; k++) {
            float s = 0.0f;
            int   cnt = 0;
            #pragma unroll
            for (int l = 0; l < 3; l++) {
                const int p = idx[k * 3 + l];
                if (p >= 0) {                 // predicated LDG + SEL (no branch)
                    s += __half2float(g_t16[l * N_NODES + p]);
                    cnt++;
                }
            }
            float inv = (cnt == 3) ? (1.0f / 3.0f)
                                   : ((cnt == 2) ? 0.5f : 1.0f);
            r[k] = s * inv;
        }

        __stcs(((float4*)out) + q, res);
    }
}

// ---------------------------------------------------------------------------
// Launch. Inputs identified by element count:
//   30,000,000 -> paths (int32 [10M,3]); 12,800,000 -> node_feature; 384 -> W
// Grid sized so ALL blocks are resident (safe device-wide spin barrier).
// ---------------------------------------------------------------------------
extern "C" void kernel_launch(void* const* d_in, const int* in_sizes, int n_in,
                              void* d_out, int out_size) {
    const void*  paths_raw = nullptr;
    const float* nf        = nullptr;
    const float* W         = nullptr;

    for (int i = 0; i < n_in; i++) {
        if      (in_sizes[i] == N_PATHS * MAX_LEN)  paths_raw = d_in[i];
        else if (in_sizes[i] == N_NODES * HIDDEN)   nf        = (const float*)d_in[i];
        else if (in_sizes[i] == MAX_LEN * HIDDEN)   W         = (const float*)d_in[i];
    }

    float* out = (float*)d_out;

    static int grid = 0;
    if (grid == 0) {
        int smCount = 0, blocksPerSM = 0;
        cudaDeviceGetAttribute(&smCount, cudaDevAttrMultiProcessorCount, 0);
        cudaOccupancyMaxActiveBlocksPerMultiprocessor(
            &blocksPerSM, fused_kernel, 256, 0);
        if (smCount <= 0)     smCount = 148;
        if (blocksPerSM <= 0) blocksPerSM = 1;
        grid = smCount * blocksPerSM;   // every block resident -> barrier safe
    }

    fused_kernel<<<grid, 256>>>(nf, W, (const int*)paths_raw, out);
}

// round 11
// speedup vs baseline: 1.0210x; 1.0210x over previous
#include <cuda_runtime.h>
#include <cuda_fp16.h>
#include <cuda_bf16.h>

// Problem constants (from reference_code)
#define N_PATHS  10000000
#define MAX_LEN  3
#define N_NODES  100000
#define HIDDEN   128

// fp16 planar projection table: g_t16[l * N_NODES + node], 600 KB total.
__device__ __half g_t16[3 * N_NODES];

// ---------------------------------------------------------------------------
// Kernel 1: proj[l][node] = dot(feature[node], W[l][0]) -> fp16 planar table.
// One warp per EIGHT nodes; all 8 feature float4 loads front-batched (MLP=8)
// to cover DRAM latency. Results are shuffled to lanes 0..23 which issue
// coalesced-group STG.U16 stores (3 groups of 8 contiguous halves).
// 100000 % 8 == 0 -> no tail guards.
// ---------------------------------------------------------------------------
__global__ void __launch_bounds__(256)
proj_kernel(const float* __restrict__ nf, const float* __restrict__ W) {
    const int lane   = threadIdx.x & 31;
    const int warpId = (blockIdx.x * blockDim.x + threadIdx.x) >> 5;
    const int n0     = warpId * 8;
    if (n0 >= N_NODES) return;

    // W rows, lane t holds dims [4t, 4t+4)
    const float4 w0 = __ldg(((const float4*)W) + 0  + lane);
    const float4 w1 = __ldg(((const float4*)W) + 32 + lane);
    const float4 w2 = __ldg(((const float4*)W) + 64 + lane);

    // Front-batched: 8 independent 512B warp requests in flight (MLP=8)
    float4 f[8];
    #pragma unroll
    for (int i = 0; i < 8; i++)
        f[i] = __ldcs(((const float4*)nf) + (size_t)(n0 + i) * 32 + lane);

    // Per-node partial dots + warp reduction; result broadcast to all lanes
    float r0[8], r1[8], r2[8];
    #pragma unroll
    for (int i = 0; i < 8; i++) {
        float s0 = f[i].x*w0.x + f[i].y*w0.y + f[i].z*w0.z + f[i].w*w0.w;
        float s1 = f[i].x*w1.x + f[i].y*w1.y + f[i].z*w1.z + f[i].w*w1.w;
        float s2 = f[i].x*w2.x + f[i].y*w2.y + f[i].z*w2.z + f[i].w*w2.w;
        #pragma unroll
        for (int o = 16; o > 0; o >>= 1) {
            s0 += __shfl_xor_sync(0xFFFFFFFFu, s0, o);
            s1 += __shfl_xor_sync(0xFFFFFFFFu, s1, o);
            s2 += __shfl_xor_sync(0xFFFFFFFFu, s2, o);
        }
        r0[i] = s0; r1[i] = s1; r2[i] = s2;  // identical across lanes
    }

    // Distributed coalesced stores: lane j in [0,8) stores plane0 node n0+j,
    // lane j in [8,16) plane1, lane j in [16,24) plane2. Each group of 8
    // lanes writes 8 contiguous halves (16B) -> 3 small coalesced STG groups.
    const int g = lane >> 3;        // 0..3
    const int j = lane & 7;         // node offset within the batch
    if (g < 3) {
        // select r{g}[j]; arrays are lane-invariant so direct index is fine
        float v = (g == 0) ? r0[0] : (g == 1) ? r1[0] : r2[0];
        // need element j: use a small select chain (arrays in regs, j dynamic
        // would spill) -> unrolled pick
        float vv[8];
        #pragma unroll
        for (int i = 0; i < 8; i++)
            vv[i] = (g == 0) ? r0[i] : (g == 1) ? r1[i] : r2[i];
        #pragma unroll
        for (int i = 0; i < 8; i++)
            if (j == i) v = vv[i];
        g_t16[g * N_NODES + n0 + j] = __float2half(v);
    }
}

// ---------------------------------------------------------------------------
// Kernel 2: gather + masked mean. BYTE-IDENTICAL logic to R7 (measured at
// the L1tex wavefront floor, ~101 us; protected).
// ---------------------------------------------------------------------------
__global__ void __launch_bounds__(256)
gather_kernel(const int* __restrict__ paths, float* __restrict__ out) {
    const long long tid = (long long)blockIdx.x * blockDim.x + threadIdx.x;
    if (tid >= (N_PATHS / 4)) return;

    const int4* p4 = ((const int4*)paths) + tid * 3;
    int4 v0 = __ldcs(p4 + 0);
    int4 v1 = __ldcs(p4 + 1);
    int4 v2 = __ldcs(p4 + 2);

    int idx[12] = { v0.x, v0.y, v0.z, v0.w,
                    v1.x, v1.y, v1.z, v1.w,
                    v2.x, v2.y, v2.z, v2.w };

    float4 res;
    float* r = (float*)&res;

    #pragma unroll
    for (int k = 0; k < 4; k++) {
        float s = 0.0f;
        int   cnt = 0;
        #pragma unroll
        for (int l = 0; l < 3; l++) {
            const int p = idx[k * 3 + l];
            if (p >= 0) {                     // predicated LDG + SEL (no branch)
                s += __half2float(g_t16[l * N_NODES + p]);
                cnt++;
            }
        }
        float inv = (cnt == 3) ? (1.0f / 3.0f)
                               : ((cnt == 2) ? 0.5f : 1.0f);
        r[k] = s * inv;
    }

    __stcs(((float4*)out) + tid, res);
}

// ---------------------------------------------------------------------------
// Launch. Inputs identified by element count:
//   30,000,000 -> paths (int32 [10M,3]); 12,800,000 -> node_feature; 384 -> W
// ---------------------------------------------------------------------------
extern "C" void kernel_launch(void* const* d_in, const int* in_sizes, int n_in,
                              void* d_out, int out_size) {
    const void*  paths_raw = nullptr;
    const float* nf        = nullptr;
    const float* W         = nullptr;

    for (int i = 0; i < n_in; i++) {
        if      (in_sizes[i] == N_PATHS * MAX_LEN)  paths_raw = d_in[i];
        else if (in_sizes[i] == N_NODES * HIDDEN)   nf        = (const float*)d_in[i];
        else if (in_sizes[i] == MAX_LEN * HIDDEN)   W         = (const float*)d_in[i];
    }

    float* out = (float*)d_out;

    // proj: one warp per 8 nodes -> 12500 warps -> 1563 blocks of 256
    {
        const int threads = 256;
        const int warps   = N_NODES / 8;                  // 12500
        const int blocks  = (warps * 32 + threads - 1) / threads;
        proj_kernel<<<blocks, threads>>>(nf, W);
    }

    // gather: 2.5M threads, 4 paths each (R7-proven launch shape)
    {
        const int threads = 256;
        const long long nThreads = N_PATHS / 4;
        const int blocks = (int)((nThreads + threads - 1) / threads);
        gather_kernel<<<blocks, threads>>>((const int*)paths_raw, out);
    }
}